// round 4
// baseline (speedup 1.0000x reference)
#include <cuda_runtime.h>
#include <cuda_bf16.h>
#include <cstdint>

// ============================================================================
// Edge-MLP via algebraic split:
//   concat(f_s,f_d) @ W1^T  ==  f_s @ W1a^T + f_d @ W1b^T
// Pass 1 (node_gemm): PQ[n] = feats[n] @ [W1a|W1b]^T  -> bf16 tables gP, gQ.
// Pass 2 (edge):      out[e] = sigmoid(w2 . relu(P[src]+Q[dst]+b1) + b2)
// GEMM is 600k->100k rows: 19.7 GMAC -> 3.3 GMAC. Edge pass is L2-BW bound.
// ============================================================================

#define MAX_NODES 100000
#define HDIM 128

__device__ __nv_bfloat16 g_P[(size_t)MAX_NODES * HDIM];
__device__ __nv_bfloat16 g_Q[(size_t)MAX_NODES * HDIM];

// ---- node_gemm smem layout: A 128x128 bf16 (stride 272), B 256x128 bf16 ----
#define SA    272u
#define OFF_A 0u
#define OFF_B (128u * SA)            // 34816
#define GEMM_SMEM (OFF_B + 256u * SA)  // 104448
#define SSTG  528u                    // stage stride (256 bf16 + 16B pad)

// ---------------------------------------------------------------------------
__device__ __forceinline__ uint32_t smem_u32(const void* p) {
    uint32_t a;
    asm("{ .reg .u64 t; cvta.to.shared.u64 t, %1; cvt.u32.u64 %0, t; }" : "=r"(a) : "l"(p));
    return a;
}
__device__ __forceinline__ void ldsm_x4(uint32_t* r, uint32_t addr) {
    asm volatile("ldmatrix.sync.aligned.m8n8.x4.shared.b16 {%0,%1,%2,%3}, [%4];"
                 : "=r"(r[0]), "=r"(r[1]), "=r"(r[2]), "=r"(r[3]) : "r"(addr));
}
__device__ __forceinline__ void mma_bf16(float* c, const uint32_t* a,
                                         uint32_t b0, uint32_t b1) {
    asm volatile(
        "mma.sync.aligned.m16n8k16.row.col.f32.bf16.bf16.f32 "
        "{%0,%1,%2,%3}, {%4,%5,%6,%7}, {%8,%9}, {%0,%1,%2,%3};"
        : "+f"(c[0]), "+f"(c[1]), "+f"(c[2]), "+f"(c[3])
        : "r"(a[0]), "r"(a[1]), "r"(a[2]), "r"(a[3]), "r"(b0), "r"(b1));
}

// ---------------------------------------------------------------------------
// Pass 1: per-tile GEMM  [128 nodes x 128 K] x [256 outs x 128 K]^T
// Tile 128x256, 16 warps m32n64, K=128 (8 mma K-steps). One tile per CTA.
// ---------------------------------------------------------------------------
__global__ __launch_bounds__(512, 1) void node_gemm_kernel(
    const float* __restrict__ feats, const float* __restrict__ W1, int nNodes)
{
    extern __shared__ char sm[];
    uint32_t sb = smem_u32(sm);
    int tid = threadIdx.x, wid = tid >> 5, lid = tid & 31;
    int row0 = blockIdx.x * 128;

    // fill A: feats rows (fp32 -> bf16), clamp OOB rows
    for (int idx = tid; idx < 128 * 64; idx += 512) {
        int r = idx >> 6, c2 = idx & 63;
        int node = row0 + r; if (node >= nNodes) node = nNodes - 1;
        float2 v = *(const float2*)(feats + (size_t)node * HDIM + c2 * 2);
        *(__nv_bfloat162*)(sm + OFF_A + (uint32_t)r * SA + (uint32_t)c2 * 4u) =
            __floats2bfloat162_rn(v.x, v.y);
    }
    // fill B: Wcat[j][k] = (j<128) ? W1[j][k] : W1[j-128][128+k]
    for (int idx = tid; idx < 256 * 64; idx += 512) {
        int j = idx >> 6, c2 = idx & 63;
        const float* wrow = W1 + (size_t)(j & 127) * 256 + ((j >> 7) << 7);
        float2 v = *(const float2*)(wrow + c2 * 2);
        *(__nv_bfloat162*)(sm + OFF_B + (uint32_t)j * SA + (uint32_t)c2 * 4u) =
            __floats2bfloat162_rn(v.x, v.y);
    }
    __syncthreads();

    // warp grid 4(M) x 4(N): warp tile m32 x n64
    int mw = wid & 3, nw = wid >> 2;
    int mbase = mw * 32, nbase = nw * 64;
    uint32_t a_lane = sb + OFF_A +
        (uint32_t)((mbase + (lid & 15)) * SA + ((lid >> 4) * 8) * 2);
    uint32_t b_lane = sb + OFF_B +
        (uint32_t)((nbase + (lid & 7) + ((lid >> 4) << 3)) * SA +
                   (((lid >> 3) & 1) * 8) * 2);

    float acc[2][8][4];
#pragma unroll
    for (int mt = 0; mt < 2; mt++)
#pragma unroll
        for (int nt = 0; nt < 8; nt++)
#pragma unroll
            for (int q = 0; q < 4; q++) acc[mt][nt][q] = 0.f;

#pragma unroll
    for (int ks = 0; ks < 8; ks++) {
        uint32_t koff = (uint32_t)ks * 32u;
        uint32_t a[2][4], b[4][4];
#pragma unroll
        for (int t = 0; t < 2; t++)
            ldsm_x4(a[t], a_lane + koff + (uint32_t)t * (16u * SA));
#pragma unroll
        for (int t = 0; t < 4; t++)
            ldsm_x4(b[t], b_lane + koff + (uint32_t)t * (16u * SA));
#pragma unroll
        for (int mt = 0; mt < 2; mt++)
#pragma unroll
            for (int nt = 0; nt < 8; nt++) {
                int bt = nt >> 1, hi = (nt & 1) << 1;
                mma_bf16(acc[mt][nt], a[mt], b[bt][hi], b[bt][hi + 1]);
            }
    }
    __syncthreads();   // B reads done; reuse B region as stage

    // stage acc -> bf16 [128 rows][256 cols], stride SSTG
#pragma unroll
    for (int mt = 0; mt < 2; mt++)
#pragma unroll
        for (int nt = 0; nt < 8; nt++) {
            int r = mbase + mt * 16 + (lid >> 2);
            int c0 = nbase + nt * 8 + 2 * (lid & 3);
            const float* c = acc[mt][nt];
            *(__nv_bfloat162*)(sm + OFF_B + (uint32_t)r * SSTG + (uint32_t)c0 * 2u) =
                __floats2bfloat162_rn(c[0], c[1]);
            *(__nv_bfloat162*)(sm + OFF_B + (uint32_t)(r + 8) * SSTG + (uint32_t)c0 * 2u) =
                __floats2bfloat162_rn(c[2], c[3]);
        }
    __syncthreads();

    // copy stage -> gP / gQ (coalesced 16B chunks)
    for (int idx = tid; idx < 128 * 32; idx += 512) {
        int r = idx >> 5, c = idx & 31;
        int node = row0 + r;
        if (node < nNodes) {
            uint4 v = *(const uint4*)(sm + OFF_B + (uint32_t)r * SSTG + (uint32_t)c * 16u);
            __nv_bfloat16* dstb = (c < 16 ? g_P : g_Q) + (size_t)node * HDIM + (c & 15) * 8;
            *(uint4*)dstb = v;
        }
    }
}

// ---------------------------------------------------------------------------
// Pass 2: per edge, 8 lanes/edge (16 cols each): relu(P[s]+Q[d]+b1).w2
// ---------------------------------------------------------------------------
__global__ __launch_bounds__(512) void edge_kernel(
    const int* __restrict__ src, const int* __restrict__ dst,
    const float* __restrict__ b1, const float* __restrict__ W2,
    const float* __restrict__ b2, float* __restrict__ out, int E)
{
    int tid = threadIdx.x, warp = tid >> 5, lid = tid & 31;
    int g = lid & 7, sub = lid >> 3;
    int e = blockIdx.x * 64 + (warp << 2) + sub;

    // per-lane constants: cols [g*16, g*16+16)
    float b1v[16], w2v[16];
#pragma unroll
    for (int i = 0; i < 8; i++) {
        float2 tb = *(const float2*)(b1 + g * 16 + 2 * i);
        float2 tw = *(const float2*)(W2 + g * 16 + 2 * i);
        b1v[2 * i] = tb.x; b1v[2 * i + 1] = tb.y;
        w2v[2 * i] = tw.x; w2v[2 * i + 1] = tw.y;
    }

    float acc = 0.f;
    if (e < E) {
        int s = __ldg(src + e), d = __ldg(dst + e);
        const uint4* pp = (const uint4*)(g_P + (size_t)s * HDIM) + 2 * g;
        const uint4* qq = (const uint4*)(g_Q + (size_t)d * HDIM) + 2 * g;
        uint4 pv[2] = {pp[0], pp[1]};
        uint4 qv[2] = {qq[0], qq[1]};
#pragma unroll
        for (int h = 0; h < 2; h++) {
            const uint32_t* pu = (const uint32_t*)&pv[h];
            const uint32_t* qu = (const uint32_t*)&qv[h];
#pragma unroll
            for (int i = 0; i < 4; i++) {
                float2 pf = __bfloat1622float2(*(const __nv_bfloat162*)&pu[i]);
                float2 qf = __bfloat1622float2(*(const __nv_bfloat162*)&qu[i]);
                int c = h * 8 + 2 * i;
                float h0 = pf.x + qf.x + b1v[c];
                float h1 = pf.y + qf.y + b1v[c + 1];
                acc = fmaf(fmaxf(h0, 0.f), w2v[c], acc);
                acc = fmaf(fmaxf(h1, 0.f), w2v[c + 1], acc);
            }
        }
    }
    // reduce across the 8 lanes of this edge
#pragma unroll
    for (int d = 4; d >= 1; d >>= 1)
        acc += __shfl_down_sync(0xFFFFFFFF, acc, d, 8);

    if (g == 0 && e < E) {
        float v = acc + __ldg(b2);
        out[e] = 1.f / (1.f + __expf(-v));
    }
}

// ---------------------------------------------------------------------------
extern "C" void kernel_launch(void* const* d_in, const int* in_sizes, int n_in,
                              void* d_out, int out_size) {
    const int*   src   = (const int*)d_in[0];
    const int*   dst   = (const int*)d_in[1];
    const float* feats = (const float*)d_in[2];
    const float* W1    = (const float*)d_in[3];
    const float* b1    = (const float*)d_in[4];
    const float* W2    = (const float*)d_in[5];
    const float* b2    = (const float*)d_in[6];
    float* out = (float*)d_out;
    int E = in_sizes[0];
    int nNodes = in_sizes[2] / HDIM;

    int ntiles = (nNodes + 127) / 128;
    cudaFuncSetAttribute(node_gemm_kernel,
                         cudaFuncAttributeMaxDynamicSharedMemorySize, GEMM_SMEM);
    node_gemm_kernel<<<ntiles, 512, GEMM_SMEM>>>(feats, W1, nNodes);

    int nblocks = (E + 63) / 64;
    edge_kernel<<<nblocks, 512>>>(src, dst, b1, W2, b2, out, E);
}

// round 5
// speedup vs baseline: 1.0183x; 1.0183x over previous
#include <cuda_runtime.h>
#include <cuda_bf16.h>
#include <cstdint>

// ============================================================================
// Edge-MLP via algebraic split:
//   concat(f_s,f_d) @ W1^T == f_s @ W1a^T + f_d @ W1b^T
// Pass 1: persistent node GEMM -> bf16 tables g_P, g_Q (W1 loaded once/CTA).
// Pass 2: persistent edge kernel, 4-stage cp.async pipeline staging P/Q rows
//         into smem, compute out[e] = sigmoid(w2 . relu(P[s]+Q[d]+b1) + b2).
// ============================================================================

#define MAX_NODES 100000
#define HDIM 128
#define NSM 148

__device__ __nv_bfloat16 g_P[(size_t)MAX_NODES * HDIM];
__device__ __nv_bfloat16 g_Q[(size_t)MAX_NODES * HDIM];

// ---- pass-1 smem layout ----
#define SA     272u                       // 128 bf16 cols + 16B pad
#define OFF_W  0u                         // 256 x 128 bf16 (Wcat)
#define OFF_A  (256u * SA)                // 69632: 128 x 128 bf16
#define OFF_STG (OFF_A + 128u * SA)       // 104448: stage 128 x 256 bf16
#define SSTG   528u
#define GEMM_SMEM (OFF_STG + 128u * SSTG) // 172032

// ---- pass-2 smem layout ----
#define TILE_E  64
#define STAGES  4
#define ESTRIDE 528u                      // P[256] | Q[256] | pad 16
#define STAGE_B (TILE_E * ESTRIDE)        // 33792
#define EDGE_SMEM (STAGES * STAGE_B)      // 135168

// ---------------------------------------------------------------------------
__device__ __forceinline__ uint32_t smem_u32(const void* p) {
    uint32_t a;
    asm("{ .reg .u64 t; cvta.to.shared.u64 t, %1; cvt.u32.u64 %0, t; }" : "=r"(a) : "l"(p));
    return a;
}
__device__ __forceinline__ void cp_async16(uint32_t saddr, const void* gaddr) {
    asm volatile("cp.async.cg.shared.global [%0], [%1], 16;"
                 :: "r"(saddr), "l"(gaddr) : "memory");
}
__device__ __forceinline__ void cp_commit() {
    asm volatile("cp.async.commit_group;" ::: "memory");
}
template <int N>
__device__ __forceinline__ void cp_wait() {
    asm volatile("cp.async.wait_group %0;" :: "n"(N) : "memory");
}
__device__ __forceinline__ void ldsm_x4(uint32_t* r, uint32_t addr) {
    asm volatile("ldmatrix.sync.aligned.m8n8.x4.shared.b16 {%0,%1,%2,%3}, [%4];"
                 : "=r"(r[0]), "=r"(r[1]), "=r"(r[2]), "=r"(r[3]) : "r"(addr));
}
__device__ __forceinline__ void mma_bf16(float* c, const uint32_t* a,
                                         uint32_t b0, uint32_t b1) {
    asm volatile(
        "mma.sync.aligned.m16n8k16.row.col.f32.bf16.bf16.f32 "
        "{%0,%1,%2,%3}, {%4,%5,%6,%7}, {%8,%9}, {%0,%1,%2,%3};"
        : "+f"(c[0]), "+f"(c[1]), "+f"(c[2]), "+f"(c[3])
        : "r"(a[0]), "r"(a[1]), "r"(a[2]), "r"(a[3]), "r"(b0), "r"(b1));
}

// ---------------------------------------------------------------------------
// Pass 1: persistent node GEMM. Tile 128 nodes x 256 outs, K=128.
// 16 warps, warp tile m32 x n64.
// ---------------------------------------------------------------------------
__global__ __launch_bounds__(512, 1) void node_gemm_kernel(
    const float* __restrict__ feats, const float* __restrict__ W1, int nNodes)
{
    extern __shared__ char sm[];
    uint32_t sb = smem_u32(sm);
    int tid = threadIdx.x, wid = tid >> 5, lid = tid & 31;

    // ---- W1 -> Wcat bf16 smem, ONCE ----
    for (int idx = tid; idx < 256 * 64; idx += 512) {
        int j = idx >> 6, c2 = idx & 63;
        const float* wrow = W1 + (size_t)(j & 127) * 256 + ((j >> 7) << 7);
        float2 v = *(const float2*)(wrow + c2 * 2);
        *(__nv_bfloat162*)(sm + OFF_W + (uint32_t)j * SA + (uint32_t)c2 * 4u) =
            __floats2bfloat162_rn(v.x, v.y);
    }

    int mw = wid & 3, nw = wid >> 2;
    int mbase = mw * 32, nbase = nw * 64;
    uint32_t a_lane = sb + OFF_A +
        (uint32_t)((mbase + (lid & 15)) * SA + ((lid >> 4) * 8) * 2);
    uint32_t b_lane = sb + OFF_W +
        (uint32_t)((nbase + (lid & 7) + ((lid >> 4) << 3)) * SA +
                   (((lid >> 3) & 1) * 8) * 2);

    int ntiles = (nNodes + 127) / 128;
    for (int t = blockIdx.x; t < ntiles; t += NSM) {
        int row0 = t * 128;
        __syncthreads();   // prior iteration done with A
        // fill A: 128 node rows fp32 -> bf16
        for (int idx = tid; idx < 128 * 64; idx += 512) {
            int r = idx >> 6, c2 = idx & 63;
            int node = row0 + r; if (node >= nNodes) node = nNodes - 1;
            float2 v = *(const float2*)(feats + (size_t)node * HDIM + c2 * 2);
            *(__nv_bfloat162*)(sm + OFF_A + (uint32_t)r * SA + (uint32_t)c2 * 4u) =
                __floats2bfloat162_rn(v.x, v.y);
        }
        __syncthreads();

        float acc[2][8][4];
#pragma unroll
        for (int mt = 0; mt < 2; mt++)
#pragma unroll
            for (int nt = 0; nt < 8; nt++)
#pragma unroll
                for (int q = 0; q < 4; q++) acc[mt][nt][q] = 0.f;

#pragma unroll
        for (int ks = 0; ks < 8; ks++) {
            uint32_t koff = (uint32_t)ks * 32u;
            uint32_t a[2][4], b[4][4];
#pragma unroll
            for (int u = 0; u < 2; u++)
                ldsm_x4(a[u], a_lane + koff + (uint32_t)u * (16u * SA));
#pragma unroll
            for (int u = 0; u < 4; u++)
                ldsm_x4(b[u], b_lane + koff + (uint32_t)u * (16u * SA));
#pragma unroll
            for (int mt = 0; mt < 2; mt++)
#pragma unroll
                for (int nt = 0; nt < 8; nt++) {
                    int bt = nt >> 1, hi = (nt & 1) << 1;
                    mma_bf16(acc[mt][nt], a[mt], b[bt][hi], b[bt][hi + 1]);
                }
        }

        // stage acc -> bf16 smem [128 x 256]
#pragma unroll
        for (int mt = 0; mt < 2; mt++)
#pragma unroll
            for (int nt = 0; nt < 8; nt++) {
                int r = mbase + mt * 16 + (lid >> 2);
                int c0 = nbase + nt * 8 + 2 * (lid & 3);
                const float* c = acc[mt][nt];
                *(__nv_bfloat162*)(sm + OFF_STG + (uint32_t)r * SSTG + (uint32_t)c0 * 2u) =
                    __floats2bfloat162_rn(c[0], c[1]);
                *(__nv_bfloat162*)(sm + OFF_STG + (uint32_t)(r + 8) * SSTG + (uint32_t)c0 * 2u) =
                    __floats2bfloat162_rn(c[2], c[3]);
            }
        __syncthreads();

        // coalesced copy-out: cols 0..255 -> P (first 16 chunks) / Q (last 16)
        for (int idx = tid; idx < 128 * 32; idx += 512) {
            int r = idx >> 5, c = idx & 31;
            int node = row0 + r;
            if (node < nNodes) {
                uint4 v = *(const uint4*)(sm + OFF_STG + (uint32_t)r * SSTG + (uint32_t)c * 16u);
                __nv_bfloat16* dstb = (c < 16 ? g_P : g_Q) + (size_t)node * HDIM + (c & 15) * 8;
                *(uint4*)dstb = v;
            }
        }
    }
}

// ---------------------------------------------------------------------------
// Pass 2: persistent edge kernel. 256 threads, 4-stage cp.async pipeline.
// Batch = 64 edges; stage holds P-row|Q-row per edge (stride 528).
// ---------------------------------------------------------------------------
__device__ __forceinline__ void fill_stage(uint32_t sb, int s,
                                           const int* __restrict__ src,
                                           const int* __restrict__ dst,
                                           int e0, int E) {
    int tid = threadIdx.x;
    int q = tid & 15, r0 = tid >> 4;
#pragma unroll
    for (int it = 0; it < 8; it++) {
        int r = it * 16 + r0;            // 0..127
        int i = r & 63;
        int isQ = r >> 6;
        int e = e0 + i; if (e >= E) e = E - 1;
        int node = isQ ? __ldg(dst + e) : __ldg(src + e);
        const char* gp = (const char*)((isQ ? g_Q : g_P) + (size_t)node * HDIM) + q * 16;
        uint32_t sp = sb + (uint32_t)s * STAGE_B + (uint32_t)i * ESTRIDE +
                      (uint32_t)(isQ << 8) + (uint32_t)q * 16u;
        cp_async16(sp, gp);
    }
    cp_commit();
}

__global__ __launch_bounds__(256, 1) void edge_kernel(
    const int* __restrict__ src, const int* __restrict__ dst,
    const float* __restrict__ b1, const float* __restrict__ W2,
    const float* __restrict__ b2, float* __restrict__ out, int E)
{
    extern __shared__ char sm[];
    uint32_t sb = smem_u32(sm);
    int tid = threadIdx.x, w = tid >> 5, lid = tid & 31;
    int g = lid & 7, sub = lid >> 3;

    // per-lane constants: cols [g*16, g*16+16)
    float b1v[16], w2v[16];
#pragma unroll
    for (int i = 0; i < 8; i++) {
        float2 tb = *(const float2*)(b1 + g * 16 + 2 * i);
        float2 tw = *(const float2*)(W2 + g * 16 + 2 * i);
        b1v[2 * i] = tb.x; b1v[2 * i + 1] = tb.y;
        w2v[2 * i] = tw.x; w2v[2 * i + 1] = tw.y;
    }
    float b2v = __ldg(b2);

    int NB = (E + TILE_E - 1) / TILE_E;
    int bx = blockIdx.x;
    int nb = (bx < NB) ? ((NB - bx - 1) / NSM + 1) : 0;

    // prologue: fill up to STAGES-1 stages
    int npro = nb < (STAGES - 1) ? nb : (STAGES - 1);
    for (int k = 0; k < npro; k++)
        fill_stage(sb, k, src, dst, (bx + k * NSM) * TILE_E, E);

    for (int k = 0; k < nb; k++) {
        int s = k & (STAGES - 1);
        int e0 = (bx + k * NSM) * TILE_E;

        if (k + (STAGES - 1) < nb) cp_wait<STAGES - 2>();
        else                        cp_wait<0>();
        __syncthreads();   // stage s data visible to all warps

        // compute 64 edges: 8 lanes/edge, 2 passes of 32 edges
        const char* stg = sm + (size_t)s * STAGE_B;
#pragma unroll
        for (int p = 0; p < 2; p++) {
            int i = w * 4 + sub + p * 32;    // edge slot
            const uint4* pp = (const uint4*)(stg + (uint32_t)i * ESTRIDE + (uint32_t)g * 32u);
            const uint4* qq = (const uint4*)(stg + (uint32_t)i * ESTRIDE + 256u + (uint32_t)g * 32u);
            uint4 pv0 = pp[0], pv1 = pp[1];
            uint4 qv0 = qq[0], qv1 = qq[1];
            float acc = 0.f;
            const uint32_t* pu0 = (const uint32_t*)&pv0;
            const uint32_t* qu0 = (const uint32_t*)&qv0;
            const uint32_t* pu1 = (const uint32_t*)&pv1;
            const uint32_t* qu1 = (const uint32_t*)&qv1;
#pragma unroll
            for (int c2 = 0; c2 < 4; c2++) {
                float2 pf = __bfloat1622float2(*(const __nv_bfloat162*)&pu0[c2]);
                float2 qf = __bfloat1622float2(*(const __nv_bfloat162*)&qu0[c2]);
                int c = 2 * c2;
                acc = fmaf(fmaxf(pf.x + qf.x + b1v[c], 0.f), w2v[c], acc);
                acc = fmaf(fmaxf(pf.y + qf.y + b1v[c + 1], 0.f), w2v[c + 1], acc);
            }
#pragma unroll
            for (int c2 = 0; c2 < 4; c2++) {
                float2 pf = __bfloat1622float2(*(const __nv_bfloat162*)&pu1[c2]);
                float2 qf = __bfloat1622float2(*(const __nv_bfloat162*)&qu1[c2]);
                int c = 8 + 2 * c2;
                acc = fmaf(fmaxf(pf.x + qf.x + b1v[c], 0.f), w2v[c], acc);
                acc = fmaf(fmaxf(pf.y + qf.y + b1v[c + 1], 0.f), w2v[c + 1], acc);
            }
#pragma unroll
            for (int d = 1; d <= 4; d <<= 1)
                acc += __shfl_xor_sync(0xFFFFFFFF, acc, d);
            if (g == 0) {
                int e = e0 + i;
                if (e < E)
                    out[e] = 1.f / (1.f + __expf(-(acc + b2v)));
            }
        }
        __syncthreads();   // all warps done with stage s before refill

        if (k + (STAGES - 1) < nb)
            fill_stage(sb, (k + STAGES - 1) & (STAGES - 1), src, dst,
                       (bx + (k + STAGES - 1) * NSM) * TILE_E, E);
    }
}

// ---------------------------------------------------------------------------
extern "C" void kernel_launch(void* const* d_in, const int* in_sizes, int n_in,
                              void* d_out, int out_size) {
    const int*   src   = (const int*)d_in[0];
    const int*   dst   = (const int*)d_in[1];
    const float* feats = (const float*)d_in[2];
    const float* W1    = (const float*)d_in[3];
    const float* b1    = (const float*)d_in[4];
    const float* W2    = (const float*)d_in[5];
    const float* b2    = (const float*)d_in[6];
    float* out = (float*)d_out;
    int E = in_sizes[0];
    int nNodes = in_sizes[2] / HDIM;

    cudaFuncSetAttribute(node_gemm_kernel,
                         cudaFuncAttributeMaxDynamicSharedMemorySize, GEMM_SMEM);
    node_gemm_kernel<<<NSM, 512, GEMM_SMEM>>>(feats, W1, nNodes);

    cudaFuncSetAttribute(edge_kernel,
                         cudaFuncAttributeMaxDynamicSharedMemorySize, EDGE_SMEM);
    edge_kernel<<<NSM, 256, EDGE_SMEM>>>(src, dst, b1, W2, b2, out, E);
}

// round 6
// speedup vs baseline: 1.7202x; 1.6894x over previous
#include <cuda_runtime.h>
#include <cuda_bf16.h>
#include <cstdint>

// ============================================================================
// Edge-MLP via algebraic split:
//   concat(f_s,f_d) @ W1^T == f_s @ W1a^T + f_d @ W1b^T
// Pass 1: persistent node GEMM -> bf16 tables g_P, g_Q (cp.async A prefetch).
// Pass 2: warp-autonomous 3-stage cp.async pipelines (no block barriers).
// ============================================================================

#define MAX_NODES 100000
#define HDIM 128
#define NSM 148

__device__ __nv_bfloat16 g_P[(size_t)MAX_NODES * HDIM];
__device__ __nv_bfloat16 g_Q[(size_t)MAX_NODES * HDIM];

// ---- pass-1 smem layout ----
#define SA      272u                        // bf16 row: 256 B + 16 pad
#define RAWS    528u                        // fp32 row: 512 B + 16 pad
#define OFF_W   0u                          // 256 x 128 bf16 Wcat
#define OFF_A   (256u * SA)                 // 69632: 128 x 128 bf16
#define OFF_RAW (OFF_A + 128u * SA)         // 104448: 128 x 128 fp32 raw
#define GEMM_SMEM (OFF_RAW + 128u * RAWS)   // 172032

// ---- pass-2 smem layout: per-warp ring ----
#define WTILE   8                           // edges per stage
#define WSTAGES 3
#define ESTRIDE 528u                        // P 256B | Q 256B | pad 16
#define WSTAGE_B (WTILE * ESTRIDE)          // 4224
#define WRING_B  (WSTAGES * WSTAGE_B)       // 12672
#define EDGE_SMEM (16u * WRING_B)           // 202752

// ---------------------------------------------------------------------------
__device__ __forceinline__ uint32_t smem_u32(const void* p) {
    uint32_t a;
    asm("{ .reg .u64 t; cvta.to.shared.u64 t, %1; cvt.u32.u64 %0, t; }" : "=r"(a) : "l"(p));
    return a;
}
__device__ __forceinline__ void cp_async16(uint32_t saddr, const void* gaddr) {
    asm volatile("cp.async.cg.shared.global [%0], [%1], 16;"
                 :: "r"(saddr), "l"(gaddr) : "memory");
}
__device__ __forceinline__ void cp_commit() {
    asm volatile("cp.async.commit_group;" ::: "memory");
}
template <int N>
__device__ __forceinline__ void cp_wait() {
    asm volatile("cp.async.wait_group %0;" :: "n"(N) : "memory");
}
__device__ __forceinline__ void ldsm_x4(uint32_t* r, uint32_t addr) {
    asm volatile("ldmatrix.sync.aligned.m8n8.x4.shared.b16 {%0,%1,%2,%3}, [%4];"
                 : "=r"(r[0]), "=r"(r[1]), "=r"(r[2]), "=r"(r[3]) : "r"(addr));
}
__device__ __forceinline__ void mma_bf16(float* c, const uint32_t* a,
                                         uint32_t b0, uint32_t b1) {
    asm volatile(
        "mma.sync.aligned.m16n8k16.row.col.f32.bf16.bf16.f32 "
        "{%0,%1,%2,%3}, {%4,%5,%6,%7}, {%8,%9}, {%0,%1,%2,%3};"
        : "+f"(c[0]), "+f"(c[1]), "+f"(c[2]), "+f"(c[3])
        : "r"(a[0]), "r"(a[1]), "r"(a[2]), "r"(a[3]), "r"(b0), "r"(b1));
}

// ---------------------------------------------------------------------------
// Pass 1: persistent node GEMM with cp.async A prefetch.
// Tile: 128 nodes x 256 outs, K=128. 16 warps, warp tile m32 x n64.
// ---------------------------------------------------------------------------
__device__ __forceinline__ void issue_raw(uint32_t sb, const float* __restrict__ feats,
                                          int row0, int nNodes) {
    int tid = threadIdx.x;
#pragma unroll
    for (int it = 0; it < 8; it++) {
        int idx = it * 512 + tid;          // 4096 chunks of 16 B
        int r = idx >> 5, c = idx & 31;
        int node = row0 + r; if (node >= nNodes) node = nNodes - 1;
        cp_async16(sb + OFF_RAW + (uint32_t)r * RAWS + (uint32_t)c * 16u,
                   (const char*)(feats + (size_t)node * HDIM) + c * 16);
    }
    cp_commit();
}

__global__ __launch_bounds__(512, 1) void node_gemm_kernel(
    const float* __restrict__ feats, const float* __restrict__ W1, int nNodes)
{
    extern __shared__ char sm[];
    uint32_t sb = smem_u32(sm);
    int tid = threadIdx.x, wid = tid >> 5, lid = tid & 31;
    int ntiles = (nNodes + 127) / 128;

    if (blockIdx.x < ntiles)
        issue_raw(sb, feats, blockIdx.x * 128, nNodes);

    // W1 -> Wcat bf16 smem, once
    for (int idx = tid; idx < 256 * 64; idx += 512) {
        int j = idx >> 6, c2 = idx & 63;
        const float* wrow = W1 + (size_t)(j & 127) * 256 + ((j >> 7) << 7);
        float2 v = *(const float2*)(wrow + c2 * 2);
        *(__nv_bfloat162*)(sm + OFF_W + (uint32_t)j * SA + (uint32_t)c2 * 4u) =
            __floats2bfloat162_rn(v.x, v.y);
    }

    int mw = wid & 3, nw = wid >> 2;
    int mbase = mw * 32, nbase = nw * 64;
    uint32_t a_lane = sb + OFF_A +
        (uint32_t)((mbase + (lid & 15)) * SA + ((lid >> 4) * 8) * 2);
    uint32_t b_lane = sb + OFF_W +
        (uint32_t)((nbase + (lid & 7) + ((lid >> 4) << 3)) * SA +
                   (((lid >> 3) & 1) * 8) * 2);

    for (int t = blockIdx.x; t < ntiles; t += NSM) {
        int row0 = t * 128;
        cp_wait<0>();
        __syncthreads();                    // raw ready; prev mma/copyout done
        // convert raw fp32 -> A bf16
        for (int idx = tid; idx < 8192; idx += 512) {
            int r = idx >> 6, c2 = idx & 63;
            float2 v = *(const float2*)(sm + OFF_RAW + (uint32_t)r * RAWS + (uint32_t)c2 * 8u);
            *(__nv_bfloat162*)(sm + OFF_A + (uint32_t)r * SA + (uint32_t)c2 * 4u) =
                __floats2bfloat162_rn(v.x, v.y);
        }
        __syncthreads();                    // A ready; raw free for refill
        if (t + NSM < ntiles)
            issue_raw(sb, feats, (t + NSM) * 128, nNodes);

        float acc[2][8][4];
#pragma unroll
        for (int mt = 0; mt < 2; mt++)
#pragma unroll
            for (int nt = 0; nt < 8; nt++)
#pragma unroll
                for (int q = 0; q < 4; q++) acc[mt][nt][q] = 0.f;

#pragma unroll
        for (int ks = 0; ks < 8; ks++) {
            uint32_t koff = (uint32_t)ks * 32u;
            uint32_t a[2][4], b[4][4];
#pragma unroll
            for (int u = 0; u < 2; u++)
                ldsm_x4(a[u], a_lane + koff + (uint32_t)u * (16u * SA));
#pragma unroll
            for (int u = 0; u < 4; u++)
                ldsm_x4(b[u], b_lane + koff + (uint32_t)u * (16u * SA));
#pragma unroll
            for (int mt = 0; mt < 2; mt++)
#pragma unroll
                for (int nt = 0; nt < 8; nt++) {
                    int bt = nt >> 1, hi = (nt & 1) << 1;
                    mma_bf16(acc[mt][nt], a[mt], b[bt][hi], b[bt][hi + 1]);
                }
        }

        // direct copy-out: cols<128 -> g_P, cols>=128 -> g_Q (bf16x2 stores)
#pragma unroll
        for (int mt = 0; mt < 2; mt++)
#pragma unroll
            for (int nt = 0; nt < 8; nt++) {
                int r = mbase + mt * 16 + (lid >> 2);
                int c0 = nbase + nt * 8 + 2 * (lid & 3);
                __nv_bfloat16* base = (c0 < 128 ? g_P : g_Q);
                int cc = c0 & 127;
                const float* c = acc[mt][nt];
                int n0 = row0 + r, n1 = row0 + r + 8;
                if (n0 < nNodes)
                    *(__nv_bfloat162*)(base + (size_t)n0 * HDIM + cc) =
                        __floats2bfloat162_rn(c[0], c[1]);
                if (n1 < nNodes)
                    *(__nv_bfloat162*)(base + (size_t)n1 * HDIM + cc) =
                        __floats2bfloat162_rn(c[2], c[3]);
            }
    }
}

// ---------------------------------------------------------------------------
// Pass 2: warp-autonomous edge pipelines. 512 thr, 16 warps/CTA, 148 CTAs.
// Each warp: private 3-stage ring of 8-edge batches; cp.async fill; no
// block barriers anywhere.
// ---------------------------------------------------------------------------
__device__ __forceinline__ void fill_batch(uint32_t wbase, int s,
                                           const int* __restrict__ src,
                                           const int* __restrict__ dst,
                                           int e0, int E) {
    int lid = threadIdx.x & 31;
    int isQ = lid >> 4;                     // lanes 0-15: P, 16-31: Q
    int q = lid & 15;
    const __nv_bfloat16* tab = isQ ? g_Q : g_P;
    const int* elist = isQ ? dst : src;
    uint32_t sp0 = wbase + (uint32_t)s * WSTAGE_B + (uint32_t)(isQ << 8) + (uint32_t)q * 16u;
#pragma unroll
    for (int it = 0; it < WTILE; it++) {
        int e = e0 + it; if (e >= E) e = E - 1;
        int node = __ldg(elist + e);
        cp_async16(sp0 + (uint32_t)it * ESTRIDE,
                   (const char*)(tab + (size_t)node * HDIM) + q * 16);
    }
    cp_commit();
}

__global__ __launch_bounds__(512, 1) void edge_kernel(
    const int* __restrict__ src, const int* __restrict__ dst,
    const float* __restrict__ b1, const float* __restrict__ W2,
    const float* __restrict__ b2, float* __restrict__ out, int E)
{
    extern __shared__ char sm[];
    uint32_t sb = smem_u32(sm);
    int tid = threadIdx.x, wid = tid >> 5, lid = tid & 31;
    int g = lid & 7, sub = lid >> 3;

    // per-lane constants: cols [g*16, g*16+16)
    float b1v[16], w2v[16];
#pragma unroll
    for (int i = 0; i < 8; i++) {
        float2 tb = *(const float2*)(b1 + g * 16 + 2 * i);
        float2 tw = *(const float2*)(W2 + g * 16 + 2 * i);
        b1v[2 * i] = tb.x; b1v[2 * i + 1] = tb.y;
        w2v[2 * i] = tw.x; w2v[2 * i + 1] = tw.y;
    }
    float b2v = __ldg(b2);

    const int NW = NSM * 16;
    int warp_g = blockIdx.x * 16 + wid;
    int NBat = (E + WTILE - 1) / WTILE;
    int nb = (warp_g < NBat) ? ((NBat - warp_g - 1) / NW + 1) : 0;
    uint32_t wbase = sb + (uint32_t)wid * WRING_B;

    if (nb > 0) fill_batch(wbase, 0, src, dst, warp_g * WTILE, E);
    if (nb > 1) fill_batch(wbase, 1, src, dst, (warp_g + NW) * WTILE, E);

    int s = 0;
    for (int k = 0; k < nb; k++) {
        int e0 = (warp_g + k * NW) * WTILE;
        if (k + 2 < nb) {
            int sn = s + 2; if (sn >= WSTAGES) sn -= WSTAGES;
            fill_batch(wbase, sn, src, dst, (warp_g + (k + 2) * NW) * WTILE, E);
            cp_wait<2>();
        } else if (k + 2 == nb) {
            cp_wait<1>();
        } else {
            cp_wait<0>();
        }
        __syncwarp();

        const char* stg = sm + (size_t)wid * WRING_B + (size_t)s * WSTAGE_B;
#pragma unroll
        for (int p = 0; p < 2; p++) {
            int i = p * 4 + sub;
            const char* row = stg + (uint32_t)i * ESTRIDE + (uint32_t)g * 32u;
            uint4 pv0 = *(const uint4*)(row);
            uint4 pv1 = *(const uint4*)(row + 16);
            uint4 qv0 = *(const uint4*)(row + 256);
            uint4 qv1 = *(const uint4*)(row + 272);
            float acc = 0.f;
            const uint32_t* pu0 = (const uint32_t*)&pv0;
            const uint32_t* qu0 = (const uint32_t*)&qv0;
            const uint32_t* pu1 = (const uint32_t*)&pv1;
            const uint32_t* qu1 = (const uint32_t*)&qv1;
#pragma unroll
            for (int c2 = 0; c2 < 4; c2++) {
                float2 pf = __bfloat1622float2(*(const __nv_bfloat162*)&pu0[c2]);
                float2 qf = __bfloat1622float2(*(const __nv_bfloat162*)&qu0[c2]);
                int c = 2 * c2;
                acc = fmaf(fmaxf(pf.x + qf.x + b1v[c], 0.f), w2v[c], acc);
                acc = fmaf(fmaxf(pf.y + qf.y + b1v[c + 1], 0.f), w2v[c + 1], acc);
            }
#pragma unroll
            for (int c2 = 0; c2 < 4; c2++) {
                float2 pf = __bfloat1622float2(*(const __nv_bfloat162*)&pu1[c2]);
                float2 qf = __bfloat1622float2(*(const __nv_bfloat162*)&qu1[c2]);
                int c = 8 + 2 * c2;
                acc = fmaf(fmaxf(pf.x + qf.x + b1v[c], 0.f), w2v[c], acc);
                acc = fmaf(fmaxf(pf.y + qf.y + b1v[c + 1], 0.f), w2v[c + 1], acc);
            }
#pragma unroll
            for (int d = 1; d <= 4; d <<= 1)
                acc += __shfl_xor_sync(0xFFFFFFFF, acc, d);
            if (g == 0) {
                int e = e0 + i;
                if (e < E)
                    out[e] = 1.f / (1.f + __expf(-(acc + b2v)));
            }
        }
        __syncwarp();      // all lanes done reading stage s before it refills
        if (++s >= WSTAGES) s = 0;
    }
}

// ---------------------------------------------------------------------------
extern "C" void kernel_launch(void* const* d_in, const int* in_sizes, int n_in,
                              void* d_out, int out_size) {
    const int*   src   = (const int*)d_in[0];
    const int*   dst   = (const int*)d_in[1];
    const float* feats = (const float*)d_in[2];
    const float* W1    = (const float*)d_in[3];
    const float* b1    = (const float*)d_in[4];
    const float* W2    = (const float*)d_in[5];
    const float* b2    = (const float*)d_in[6];
    float* out = (float*)d_out;
    int E = in_sizes[0];
    int nNodes = in_sizes[2] / HDIM;

    cudaFuncSetAttribute(node_gemm_kernel,
                         cudaFuncAttributeMaxDynamicSharedMemorySize, GEMM_SMEM);
    node_gemm_kernel<<<NSM, 512, GEMM_SMEM>>>(feats, W1, nNodes);

    cudaFuncSetAttribute(edge_kernel,
                         cudaFuncAttributeMaxDynamicSharedMemorySize, EDGE_SMEM);
    edge_kernel<<<NSM, 512, EDGE_SMEM>>>(src, dst, b1, W2, b2, out, E);
}

// round 7
// speedup vs baseline: 1.7879x; 1.0394x over previous
#include <cuda_runtime.h>
#include <cuda_bf16.h>
#include <cstdint>

// ============================================================================
// Edge-MLP via algebraic split:
//   concat(f_s,f_d) @ W1^T == f_s @ W1a^T + f_d @ W1b^T
// Pass 1: persistent node GEMM -> bf16 tables g_P (+b1 folded), g_Q.
// Pass 2: warp-autonomous 3-stage cp.async pipelines; edge indices prefetched
//         2 batches ahead via one warp-wide LDG + shfl distribution.
// ============================================================================

#define MAX_NODES 100000
#define HDIM 128
#define NSM 148

__device__ __nv_bfloat16 g_P[(size_t)MAX_NODES * HDIM];   // P + b1 (bf16)
__device__ __nv_bfloat16 g_Q[(size_t)MAX_NODES * HDIM];

// ---- pass-1 smem layout ----
#define SA      272u                        // bf16 row: 256 B + 16 pad
#define RAWS    528u                        // fp32 row: 512 B + 16 pad
#define OFF_W   0u                          // 256 x 128 bf16 Wcat
#define OFF_A   (256u * SA)                 // 69632
#define OFF_RAW (OFF_A + 128u * SA)         // 104448
#define OFF_B1  (OFF_RAW + 128u * RAWS)     // 172032: float[128]
#define GEMM_SMEM (OFF_B1 + 512u)           // 172544

// ---- pass-2 smem: per-warp ring, no pad (8x32B reads are conflict-free) ----
#define WTILE    8
#define WSTAGES  3
#define ESTRIDE  512u                       // P 256B | Q 256B
#define WSTAGE_B (WTILE * ESTRIDE)          // 4096
#define WRING_B  (WSTAGES * WSTAGE_B)       // 12288
#define EDGE_SMEM (16u * WRING_B)           // 196608

// ---------------------------------------------------------------------------
__device__ __forceinline__ uint32_t smem_u32(const void* p) {
    uint32_t a;
    asm("{ .reg .u64 t; cvta.to.shared.u64 t, %1; cvt.u32.u64 %0, t; }" : "=r"(a) : "l"(p));
    return a;
}
__device__ __forceinline__ void cp_async16(uint32_t saddr, const void* gaddr) {
    asm volatile("cp.async.cg.shared.global [%0], [%1], 16;"
                 :: "r"(saddr), "l"(gaddr) : "memory");
}
__device__ __forceinline__ void cp_commit() {
    asm volatile("cp.async.commit_group;" ::: "memory");
}
template <int N>
__device__ __forceinline__ void cp_wait() {
    asm volatile("cp.async.wait_group %0;" :: "n"(N) : "memory");
}
__device__ __forceinline__ void ldsm_x4(uint32_t* r, uint32_t addr) {
    asm volatile("ldmatrix.sync.aligned.m8n8.x4.shared.b16 {%0,%1,%2,%3}, [%4];"
                 : "=r"(r[0]), "=r"(r[1]), "=r"(r[2]), "=r"(r[3]) : "r"(addr));
}
__device__ __forceinline__ void mma_bf16(float* c, const uint32_t* a,
                                         uint32_t b0, uint32_t b1) {
    asm volatile(
        "mma.sync.aligned.m16n8k16.row.col.f32.bf16.bf16.f32 "
        "{%0,%1,%2,%3}, {%4,%5,%6,%7}, {%8,%9}, {%0,%1,%2,%3};"
        : "+f"(c[0]), "+f"(c[1]), "+f"(c[2]), "+f"(c[3])
        : "r"(a[0]), "r"(a[1]), "r"(a[2]), "r"(a[3]), "r"(b0), "r"(b1));
}

// ---------------------------------------------------------------------------
// Pass 1: persistent node GEMM with cp.async A prefetch. b1 folded into P.
// ---------------------------------------------------------------------------
__device__ __forceinline__ void issue_raw(uint32_t sb, const float* __restrict__ feats,
                                          int row0, int nNodes) {
    int tid = threadIdx.x;
#pragma unroll
    for (int it = 0; it < 8; it++) {
        int idx = it * 512 + tid;
        int r = idx >> 5, c = idx & 31;
        int node = row0 + r; if (node >= nNodes) node = nNodes - 1;
        cp_async16(sb + OFF_RAW + (uint32_t)r * RAWS + (uint32_t)c * 16u,
                   (const char*)(feats + (size_t)node * HDIM) + c * 16);
    }
    cp_commit();
}

__global__ __launch_bounds__(512, 1) void node_gemm_kernel(
    const float* __restrict__ feats, const float* __restrict__ W1,
    const float* __restrict__ b1, int nNodes)
{
    extern __shared__ char sm[];
    uint32_t sb = smem_u32(sm);
    int tid = threadIdx.x, wid = tid >> 5, lid = tid & 31;
    int ntiles = (nNodes + 127) / 128;

    if (blockIdx.x < ntiles)
        issue_raw(sb, feats, blockIdx.x * 128, nNodes);

    if (tid < 128) ((float*)(sm + OFF_B1))[tid] = b1[tid];

    // W1 -> Wcat bf16 smem, once
    for (int idx = tid; idx < 256 * 64; idx += 512) {
        int j = idx >> 6, c2 = idx & 63;
        const float* wrow = W1 + (size_t)(j & 127) * 256 + ((j >> 7) << 7);
        float2 v = *(const float2*)(wrow + c2 * 2);
        *(__nv_bfloat162*)(sm + OFF_W + (uint32_t)j * SA + (uint32_t)c2 * 4u) =
            __floats2bfloat162_rn(v.x, v.y);
    }

    int mw = wid & 3, nw = wid >> 2;
    int mbase = mw * 32, nbase = nw * 64;
    uint32_t a_lane = sb + OFF_A +
        (uint32_t)((mbase + (lid & 15)) * SA + ((lid >> 4) * 8) * 2);
    uint32_t b_lane = sb + OFF_W +
        (uint32_t)((nbase + (lid & 7) + ((lid >> 4) << 3)) * SA +
                   (((lid >> 3) & 1) * 8) * 2);

    for (int t = blockIdx.x; t < ntiles; t += NSM) {
        int row0 = t * 128;
        cp_wait<0>();
        __syncthreads();
        for (int idx = tid; idx < 8192; idx += 512) {
            int r = idx >> 6, c2 = idx & 63;
            float2 v = *(const float2*)(sm + OFF_RAW + (uint32_t)r * RAWS + (uint32_t)c2 * 8u);
            *(__nv_bfloat162*)(sm + OFF_A + (uint32_t)r * SA + (uint32_t)c2 * 4u) =
                __floats2bfloat162_rn(v.x, v.y);
        }
        __syncthreads();
        if (t + NSM < ntiles)
            issue_raw(sb, feats, (t + NSM) * 128, nNodes);

        float acc[2][8][4];
#pragma unroll
        for (int mt = 0; mt < 2; mt++)
#pragma unroll
            for (int nt = 0; nt < 8; nt++)
#pragma unroll
                for (int q = 0; q < 4; q++) acc[mt][nt][q] = 0.f;

#pragma unroll
        for (int ks = 0; ks < 8; ks++) {
            uint32_t koff = (uint32_t)ks * 32u;
            uint32_t a[2][4], b[4][4];
#pragma unroll
            for (int u = 0; u < 2; u++)
                ldsm_x4(a[u], a_lane + koff + (uint32_t)u * (16u * SA));
#pragma unroll
            for (int u = 0; u < 4; u++)
                ldsm_x4(b[u], b_lane + koff + (uint32_t)u * (16u * SA));
#pragma unroll
            for (int mt = 0; mt < 2; mt++)
#pragma unroll
                for (int nt = 0; nt < 8; nt++) {
                    int bt = nt >> 1, hi = (nt & 1) << 1;
                    mma_bf16(acc[mt][nt], a[mt], b[bt][hi], b[bt][hi + 1]);
                }
        }

        // copy-out: cols<128 -> g_P (+b1), cols>=128 -> g_Q
        const float* b1s = (const float*)(sm + OFF_B1);
#pragma unroll
        for (int mt = 0; mt < 2; mt++)
#pragma unroll
            for (int nt = 0; nt < 8; nt++) {
                int r = mbase + mt * 16 + (lid >> 2);
                int c0 = nbase + nt * 8 + 2 * (lid & 3);
                int isP = (c0 < 128);
                int cc = c0 & 127;
                float bA = isP ? b1s[cc] : 0.f;
                float bB = isP ? b1s[cc + 1] : 0.f;
                __nv_bfloat16* base = isP ? g_P : g_Q;
                const float* c = acc[mt][nt];
                int n0 = row0 + r, n1 = row0 + r + 8;
                if (n0 < nNodes)
                    *(__nv_bfloat162*)(base + (size_t)n0 * HDIM + cc) =
                        __floats2bfloat162_rn(c[0] + bA, c[1] + bB);
                if (n1 < nNodes)
                    *(__nv_bfloat162*)(base + (size_t)n1 * HDIM + cc) =
                        __floats2bfloat162_rn(c[2] + bA, c[3] + bB);
            }
    }
}

// ---------------------------------------------------------------------------
// Pass 2: warp-autonomous edge pipelines, prefetched indices.
// ---------------------------------------------------------------------------
__device__ __forceinline__ int load_idx(const int* __restrict__ src,
                                        const int* __restrict__ dst,
                                        int e0, int E, int lid) {
    int l = lid & 15;
    int e = e0 + (l & 7); if (e >= E) e = E - 1;
    return (l < 8) ? __ldg(src + e) : __ldg(dst + e);
}

__device__ __forceinline__ void fill_batch(uint32_t wbase, int s, int idxreg, int lid) {
    int isQ = lid >> 4;                 // lanes 0-15: P, 16-31: Q
    int q = lid & 15;
    const __nv_bfloat16* tab = isQ ? g_Q : g_P;
    uint32_t sp0 = wbase + (uint32_t)s * WSTAGE_B + (uint32_t)(isQ << 8) + (uint32_t)q * 16u;
#pragma unroll
    for (int it = 0; it < WTILE; it++) {
        int node = __shfl_sync(0xFFFFFFFF, idxreg, it + (isQ << 3));
        cp_async16(sp0 + (uint32_t)it * ESTRIDE,
                   (const char*)(tab + (size_t)node * HDIM) + q * 16);
    }
    cp_commit();
}

__global__ __launch_bounds__(512, 1) void edge_kernel(
    const int* __restrict__ src, const int* __restrict__ dst,
    const float* __restrict__ W2, const float* __restrict__ b2,
    float* __restrict__ out, int E)
{
    extern __shared__ char sm[];
    uint32_t sb = smem_u32(sm);
    int tid = threadIdx.x, wid = tid >> 5, lid = tid & 31;
    int g = lid & 7, sub = lid >> 3;

    float w2v[16];
#pragma unroll
    for (int i = 0; i < 8; i++) {
        float2 tw = *(const float2*)(W2 + g * 16 + 2 * i);
        w2v[2 * i] = tw.x; w2v[2 * i + 1] = tw.y;
    }
    float b2v = __ldg(b2);

    const int NW = NSM * 16;
    int warp_g = blockIdx.x * 16 + wid;
    int NBat = (E + WTILE - 1) / WTILE;
    int nb = (warp_g < NBat) ? ((NBat - warp_g - 1) / NW + 1) : 0;
    uint32_t wbase = sb + (uint32_t)wid * WRING_B;

    if (nb > 0) fill_batch(wbase, 0, load_idx(src, dst, warp_g * WTILE, E, lid), lid);
    if (nb > 1) fill_batch(wbase, 1, load_idx(src, dst, (warp_g + NW) * WTILE, E, lid), lid);
    int idxA = (nb > 2) ? load_idx(src, dst, (warp_g + 2 * NW) * WTILE, E, lid) : 0;
    int idxB = (nb > 3) ? load_idx(src, dst, (warp_g + 3 * NW) * WTILE, E, lid) : 0;

    int s = 0;
    for (int k = 0; k < nb; k++) {
        int e0 = (warp_g + k * NW) * WTILE;
        if (k + 2 < nb) {
            int sn = s + 2; if (sn >= WSTAGES) sn -= WSTAGES;
            fill_batch(wbase, sn, (k & 1) ? idxB : idxA, lid);
            if (k + 4 < nb) {
                int nidx = load_idx(src, dst, (warp_g + (k + 4) * NW) * WTILE, E, lid);
                if (k & 1) idxB = nidx; else idxA = nidx;
            }
            cp_wait<2>();
        } else if (k + 2 == nb) {
            cp_wait<1>();
        } else {
            cp_wait<0>();
        }
        __syncwarp();

        const char* stg = sm + (size_t)wid * WRING_B + (size_t)s * WSTAGE_B;
#pragma unroll
        for (int p = 0; p < 2; p++) {
            int i = p * 4 + sub;
            const char* row = stg + (uint32_t)i * ESTRIDE + (uint32_t)g * 32u;
            uint4 pv0 = *(const uint4*)(row);
            uint4 pv1 = *(const uint4*)(row + 16);
            uint4 qv0 = *(const uint4*)(row + 256);
            uint4 qv1 = *(const uint4*)(row + 272);
            float acc = 0.f;
            const uint32_t* pu0 = (const uint32_t*)&pv0;
            const uint32_t* qu0 = (const uint32_t*)&qv0;
            const uint32_t* pu1 = (const uint32_t*)&pv1;
            const uint32_t* qu1 = (const uint32_t*)&qv1;
#pragma unroll
            for (int c2 = 0; c2 < 4; c2++) {
                float2 pf = __bfloat1622float2(*(const __nv_bfloat162*)&pu0[c2]);
                float2 qf = __bfloat1622float2(*(const __nv_bfloat162*)&qu0[c2]);
                int c = 2 * c2;
                acc = fmaf(fmaxf(pf.x + qf.x, 0.f), w2v[c], acc);
                acc = fmaf(fmaxf(pf.y + qf.y, 0.f), w2v[c + 1], acc);
            }
#pragma unroll
            for (int c2 = 0; c2 < 4; c2++) {
                float2 pf = __bfloat1622float2(*(const __nv_bfloat162*)&pu1[c2]);
                float2 qf = __bfloat1622float2(*(const __nv_bfloat162*)&qu1[c2]);
                int c = 8 + 2 * c2;
                acc = fmaf(fmaxf(pf.x + qf.x, 0.f), w2v[c], acc);
                acc = fmaf(fmaxf(pf.y + qf.y, 0.f), w2v[c + 1], acc);
            }
#pragma unroll
            for (int d = 1; d <= 4; d <<= 1)
                acc += __shfl_xor_sync(0xFFFFFFFF, acc, d);
            if (g == 0) {
                int e = e0 + i;
                if (e < E)
                    out[e] = 1.f / (1.f + __expf(-(acc + b2v)));
            }
        }
        __syncwarp();
        if (++s >= WSTAGES) s = 0;
    }
}

// ---------------------------------------------------------------------------
extern "C" void kernel_launch(void* const* d_in, const int* in_sizes, int n_in,
                              void* d_out, int out_size) {
    const int*   src   = (const int*)d_in[0];
    const int*   dst   = (const int*)d_in[1];
    const float* feats = (const float*)d_in[2];
    const float* W1    = (const float*)d_in[3];
    const float* b1    = (const float*)d_in[4];
    const float* W2    = (const float*)d_in[5];
    const float* b2    = (const float*)d_in[6];
    float* out = (float*)d_out;
    int E = in_sizes[0];
    int nNodes = in_sizes[2] / HDIM;

    cudaFuncSetAttribute(node_gemm_kernel,
                         cudaFuncAttributeMaxDynamicSharedMemorySize, GEMM_SMEM);
    node_gemm_kernel<<<NSM, 512, GEMM_SMEM>>>(feats, W1, b1, nNodes);

    cudaFuncSetAttribute(edge_kernel,
                         cudaFuncAttributeMaxDynamicSharedMemorySize, EDGE_SMEM);
    edge_kernel<<<NSM, 512, EDGE_SMEM>>>(src, dst, W2, b2, out, E);
}